// round 1
// baseline (speedup 1.0000x reference)
#include <cuda_runtime.h>

#define BB 4096
#define LL 200
#define DD 64

// Precomputed fused projection matrix: M = W_item^T @ W_target  [D, D]
__device__ float g_M[DD * DD];

// M[d][dp] = sum_e W_item[e][d] * W_target[e][dp]
__global__ void precompute_M_kernel(const float* __restrict__ W_target,
                                    const float* __restrict__ W_item) {
    int d  = blockIdx.x;    // 0..63
    int dp = threadIdx.x;   // 0..63
    float s = 0.f;
    #pragma unroll
    for (int e = 0; e < DD; ++e)
        s += W_item[e * DD + d] * W_target[e * DD + dp];
    g_M[d * DD + dp] = s;
}

__global__ __launch_bounds__(256, 6) void target_attn_kernel(
    const float* __restrict__ tk,    // [B, D]  target_key
    const float* __restrict__ ik,    // [B, L, D] item_keys
    const float* __restrict__ iv,    // [B, L, D] item_values
    const int*   __restrict__ mask,  // [B, L]
    const float* __restrict__ Wv,    // [D, D]  W_value
    float* __restrict__ out)         // [B, D]
{
    const int b    = blockIdx.x;
    const int tid  = threadIdx.x;
    const int warp = tid >> 5;
    const int lane = tid & 31;

    __shared__ float s_vec[DD];        // tk, later vbar
    __shared__ float s_qk[DD];         // fused query (pre-scaled)
    __shared__ float s_w[LL];          // scores -> exp weights
    __shared__ float s_red[8];
    __shared__ float s_vpart[8][DD];   // per-warp vbar partials

    // ---- load tk, compute qk = (M @ tk) * (1/sqrt(D)) ----
    if (tid < DD) s_vec[tid] = tk[b * DD + tid];
    __syncthreads();
    if (tid < DD) {
        float s = 0.f;
        #pragma unroll
        for (int j = 0; j < DD; ++j) s += g_M[tid * DD + j] * s_vec[j];
        s_qk[tid] = s * 0.125f;   // 1/sqrt(64)
    }
    __syncthreads();

    // ---- scores[l] = qk . ik[b,l,:]  (warp per item, float2 lanes) ----
    const float2 q2 = reinterpret_cast<const float2*>(s_qk)[lane];
    const float2* ikb = reinterpret_cast<const float2*>(ik + (size_t)b * LL * DD);
    for (int l = warp; l < LL; l += 8) {
        float2 a = ikb[l * 32 + lane];
        float s = a.x * q2.x + a.y * q2.y;
        #pragma unroll
        for (int o = 16; o; o >>= 1) s += __shfl_down_sync(0xffffffffu, s, o);
        if (lane == 0) {
            int m = mask[b * LL + l];
            s_w[l] = m ? s : (s - 1e8f);
        }
    }
    __syncthreads();

    // ---- softmax over L=200 ----
    float mx = -3.0e38f;
    for (int l = tid; l < LL; l += 256) mx = fmaxf(mx, s_w[l]);
    #pragma unroll
    for (int o = 16; o; o >>= 1) mx = fmaxf(mx, __shfl_down_sync(0xffffffffu, mx, o));
    if (lane == 0) s_red[warp] = mx;
    __syncthreads();
    if (tid == 0) {
        float m2 = s_red[0];
        #pragma unroll
        for (int i = 1; i < 8; ++i) m2 = fmaxf(m2, s_red[i]);
        s_red[0] = m2;
    }
    __syncthreads();
    mx = s_red[0];
    __syncthreads();                      // everyone has mx before s_red reuse

    float sum = 0.f;
    for (int l = tid; l < LL; l += 256) {
        float e = __expf(s_w[l] - mx);
        s_w[l] = e;
        sum += e;
    }
    #pragma unroll
    for (int o = 16; o; o >>= 1) sum += __shfl_down_sync(0xffffffffu, sum, o);
    if (lane == 0) s_red[warp] = sum;
    __syncthreads();
    if (tid == 0) {
        float t = 0.f;
        #pragma unroll
        for (int i = 0; i < 8; ++i) t += s_red[i];
        s_red[0] = 1.f / t;
    }
    __syncthreads();
    const float inv = s_red[0];

    // ---- vbar[d] = sum_l w[l] * iv[b,l,d]   (warp = 25 contiguous rows) ----
    const float2* ivb = reinterpret_cast<const float2*>(iv + (size_t)b * LL * DD);
    float2 acc = make_float2(0.f, 0.f);
    const int l0 = warp * 25;
    #pragma unroll 5
    for (int l = l0; l < l0 + 25; ++l) {
        float wl = s_w[l];
        float2 v = ivb[l * 32 + lane];
        acc.x += wl * v.x;
        acc.y += wl * v.y;
    }
    s_vpart[warp][2 * lane]     = acc.x;
    s_vpart[warp][2 * lane + 1] = acc.y;
    __syncthreads();

    if (tid < DD) {
        float vb = 0.f;
        #pragma unroll
        for (int p = 0; p < 8; ++p) vb += s_vpart[p][tid];
        s_vec[tid] = vb * inv;            // normalized vbar
    }
    __syncthreads();

    // ---- out = W_value @ vbar ----
    if (tid < DD) {
        float s = 0.f;
        #pragma unroll
        for (int j = 0; j < DD; ++j) s += Wv[tid * DD + j] * s_vec[j];
        out[b * DD + tid] = s;
    }
}

extern "C" void kernel_launch(void* const* d_in, const int* in_sizes, int n_in,
                              void* d_out, int out_size) {
    const float* target_key  = (const float*)d_in[0];
    const float* item_keys   = (const float*)d_in[1];
    const float* item_values = (const float*)d_in[2];
    const int*   mask        = (const int*)  d_in[3];
    const float* W_target    = (const float*)d_in[4];
    const float* W_item      = (const float*)d_in[5];
    const float* W_value     = (const float*)d_in[6];
    float* out = (float*)d_out;

    precompute_M_kernel<<<DD, DD>>>(W_target, W_item);
    target_attn_kernel<<<BB, 256>>>(target_key, item_keys, item_values,
                                    mask, W_value, out);
}